// round 13
// baseline (speedup 1.0000x reference)
#include <cuda_runtime.h>
#include <cuda_fp16.h>
#include <math.h>
#include <stdint.h>

#define N_NODES 1024
#define SEQ     64
#define NEDGE   4096
#define NS      (N_NODES*SEQ)   /* 65536  */
#define ES      (NEDGE*SEQ)     /* 262144 */

// ---------------- scratch (device globals) ----------------
__device__ __half g_xh[NS*256];
__device__ __half g_nfh[NS*128];
__device__ __half g_PQh[NS*512];
__device__ float  g_agg[NS*128];
__device__ __half g_gatesh[NS*512];
__device__ __half g_Winh[128*256];
__device__ __half g_W1ph[2*512*128];
__device__ __half g_W2h[2*256*256];
__device__ __half g_NW1h[2*128*256];
__device__ __half g_NW2h[2*128*128];
__device__ __half g_Wihh[512*128];
__device__ __half g_Whhh[512*128];
__device__ float  g_invdeg[N_NODES];
__device__ float  g_h[N_NODES*128];
__device__ float  g_bsum[512];

// ---------------- helpers ----------------
__device__ __forceinline__ float eluf(float v){ return v > 0.f ? v : (__expf(v) - 1.f); }
__device__ __forceinline__ float sigf(float v){ return 1.f/(1.f+__expf(-v)); }
__device__ __forceinline__ float tanhfast(float v){ return 1.f - 2.f/(__expf(2.f*v)+1.f); }
__device__ __forceinline__ uint32_t f2h2(float lo, float hi){
    __half2 h = __floats2half2_rn(lo, hi);
    return *(uint32_t*)&h;
}
__device__ __forceinline__ void mma16(float4 &d, const uint32_t a[4], uint32_t b0, uint32_t b1){
    asm volatile("mma.sync.aligned.m16n8k16.row.col.f32.f16.f16.f32 "
        "{%0,%1,%2,%3}, {%4,%5,%6,%7}, {%8,%9}, {%0,%1,%2,%3};\n"
        : "+f"(d.x), "+f"(d.y), "+f"(d.z), "+f"(d.w)
        : "r"(a[0]), "r"(a[1]), "r"(a[2]), "r"(a[3]), "r"(b0), "r"(b1));
}
__device__ __forceinline__ void ldsm4(uint32_t &r0, uint32_t &r1, uint32_t &r2, uint32_t &r3, uint32_t addr){
    asm volatile("ldmatrix.sync.aligned.m8n8.x4.shared.b16 {%0,%1,%2,%3}, [%4];"
        : "=r"(r0), "=r"(r1), "=r"(r2), "=r"(r3) : "r"(addr));
}
__device__ __forceinline__ void redv2(float* p, float v0, float v1){
    asm volatile("red.global.add.v2.f32 [%0], {%1, %2};" :: "l"(p), "f"(v0), "f"(v1) : "memory");
}
__device__ __forceinline__ void cpa16(uint32_t dst, const void* src){
    asm volatile("cp.async.cg.shared.global [%0], [%1], 16;" :: "r"(dst), "l"(src));
}
#define CP_COMMIT() asm volatile("cp.async.commit_group;" ::: "memory")
#define CP_WAIT0()  asm volatile("cp.async.wait_group 0;" ::: "memory")
#define CP_WAIT1()  asm volatile("cp.async.wait_group 1;" ::: "memory")
// swizzled 16B-atom byte offset, 2 rows per 128B line, 4 k-atoms per row
__device__ __forceinline__ int swatom(int r, int katom){
    return (r>>1)*128 + ((((r&1)*4 + katom) ^ ((r>>1)&7))<<4);
}

// ================= mega-combo: weight prep + bsum + degree + build_x + zero agg =================
// blocks [0,256):          weight conversion + bsum
// blocks [256,260):        brute-force degree (1024 threads scan all dst)
// blocks [260,260+32768):  build_x (half2-vectorized)
// blocks [33028,33028+8192): zero g_agg (float4)
#define COMBO_BLOCKS (256 + 4 + 32768 + 8192)
__global__ void k_combo(const float* __restrict__ W_in,
                        const float* __restrict__ Wih, const float* __restrict__ Whh,
                        const float* __restrict__ bih, const float* __restrict__ bhh,
                        const float* __restrict__ aW1, const float* __restrict__ aW2,
                        const float* __restrict__ nW1, const float* __restrict__ nW2,
                        const float* __restrict__ itime, const float* __restrict__ iev,
                        const int* __restrict__ ann, const float* __restrict__ emb,
                        const int* __restrict__ dstp)
{
    int b = blockIdx.x, tid = threadIdx.x;
    if(b < 256){
        int i = b*256 + tid;              // 0..65535
        if(i < 128*256) g_Winh[i] = __float2half(W_in[i]);
        g_Wihh[i] = __float2half(Wih[i]);
        g_Whhh[i] = __float2half(Whh[i]);
        if(i < 512) g_bsum[i] = bih[i] + bhh[i];
#pragma unroll
        for(int l=0; l<2; l++){
            const float* W1 = aW1 + (size_t)l*65536;
            int o = i >> 8, k = i & 255;
            __half v = __float2half(W1[i]);
            if(k < 128) g_W1ph[l*65536 + o*128 + k] = v;
            else        g_W1ph[l*65536 + (256+o)*128 + (k-128)] = v;
            g_W2h[l*65536 + i] = __float2half(aW2[(size_t)l*65536 + i]);
            if(i < 128*256) g_NW1h[l*32768 + i] = __float2half(nW1[(size_t)l*32768 + i]);
            if(i < 128*128) g_NW2h[l*16384 + i] = __float2half(nW2[(size_t)l*16384 + i]);
        }
    } else if(b < 260){
        int n = (b-256)*256 + tid;        // 0..1023
        int c = 0;
        for(int e=0; e<NEDGE; e++) c += (__ldg(&dstp[e]) == n);
        g_invdeg[n] = 1.f/fmaxf((float)c, 1.f);
    } else if(b < 260 + 32768){
        int idx = (b-260)*256 + tid;      // over NS*128 half2
        int row = idx >> 7, cp = idx & 127;
        float e = __ldg(&iev[row]);
        __half2 o;
        if(cp < 63){
            const float* ep = emb + (size_t)__ldg(&ann[row])*127 + cp*2;
            o = __floats2half2_rn(__ldg(ep), __ldg(ep+1));
        } else if(cp == 63){
            o = __floats2half2_rn(__ldg(&emb[(size_t)__ldg(&ann[row])*127 + 126]), e);
        } else {
            int jj = cp - 64;
            float pos = exp2f(13.287712379549449f * (float)jj * (1.0f/64.0f));
            float r = __ldg(&itime[row]) / pos;
            float sv = __sinf(r), cv = __cosf(r);
            if(e == 0.f){ sv = 0.f; cv = 0.f; }
            o = __floats2half2_rn(sv, cv);
        }
        *(__half2*)&g_xh[(size_t)idx*2] = o;
    } else {
        size_t idx = (size_t)(b - 260 - 32768)*256 + tid;   // NS*128/4 float4
        ((float4*)g_agg)[idx] = make_float4(0.f,0.f,0.f,0.f);
    }
}

// ================= generic FP16 tensor-core GEMM (cp.async) =================
// non-NODEA: 3-stage pipeline; NODEA (A built on the fly from fp32 agg): 2-stage.
template<int ACT, bool BIAS, bool OUTH, bool NODEA>
__global__ void __launch_bounds__(256)
k_gemm(const __half* __restrict__ A, int lda,
       const float* __restrict__ aggf, const float* __restrict__ invdeg,
       const float* __restrict__ nb1,
       const __half* __restrict__ B, int ldb,
       const float* __restrict__ bias,
       void* __restrict__ Cp, int ldc, int K)
{
    __shared__ __align__(16) char sm[3*16384];
    const int m0 = blockIdx.x*128, n0 = blockIdx.y*128;
    const int tid  = threadIdx.x;
    const int warp = tid >> 5, lane = tid & 31;
    const int wm = (warp >> 1)*32;
    const int wn = (warp &  1)*64;
    const int qr = lane >> 2, qc = lane & 3;
    const uint32_t smbase = (uint32_t)__cvta_generic_to_shared(sm);

    const int j  = lane >> 3, rl = lane & 7;
    const int aj = j >> 1;
    const int bj = j & 1;
    int abase[2], asw[2], amb[2];
#pragma unroll
    for(int mi=0; mi<2; mi++){
        int m = wm + mi*16 + (j&1)*8 + rl;
        abase[mi] = (m>>1)*128; asw[mi] = (m>>1)&7; amb[mi] = (m&1)*4;
    }
    int bbase[4], bsw[4], bmb[4];
#pragma unroll
    for(int p=0; p<4; p++){
        int n = wn + p*16 + (j>>1)*8 + rl;
        bbase[p] = (n>>1)*128; bsw[p] = (n>>1)&7; bmb[p] = (n&1)*4;
    }

    float4 acc[2][8];
#pragma unroll
    for(int mi=0;mi<2;mi++)
#pragma unroll
        for(int ni=0;ni<8;ni++) acc[mi][ni] = make_float4(0.f,0.f,0.f,0.f);

    const int lr = tid >> 2;
    const int lc = (tid & 3) * 8;
    const int lk = tid & 3;

    uint4 raN[2];

    auto buildA = [&](int k0){
#pragma unroll
        for(int it=0; it<2; it++){
            int r = lr + it*64;
            const float* p = &aggf[(size_t)(m0+r)*128 + k0 + lc];
            float sc = __ldg(&invdeg[(m0+r) >> 6]);
            float4 v0 = *(const float4*)p;
            float4 v1 = *(const float4*)(p+4);
            float4 b0 = *(const float4*)&nb1[k0+lc];
            float4 b1v = *(const float4*)&nb1[k0+lc+4];
            raN[it] = make_uint4(
                f2h2(eluf(v0.x*sc+b0.x),  eluf(v0.y*sc+b0.y)),
                f2h2(eluf(v0.z*sc+b0.z),  eluf(v0.w*sc+b0.w)),
                f2h2(eluf(v1.x*sc+b1v.x), eluf(v1.y*sc+b1v.y)),
                f2h2(eluf(v1.z*sc+b1v.z), eluf(v1.w*sc+b1v.w)));
        }
    };
    auto storeA = [&](int st){
#pragma unroll
        for(int it=0; it<2; it++)
            *(uint4*)(sm + st*16384 + swatom(lr + it*64, lk)) = raN[it];
    };
    auto cpA = [&](int k0, int st){
#pragma unroll
        for(int it=0; it<2; it++){
            int r = lr + it*64;
            cpa16(smbase + st*16384 + swatom(r, lk), &A[(size_t)(m0+r)*lda + k0 + lc]);
        }
    };
    auto cpB = [&](int k0, int st){
#pragma unroll
        for(int it=0; it<2; it++){
            int r = lr + it*64;
            cpa16(smbase + st*16384 + 8192 + swatom(r, lk), &B[(size_t)(n0+r)*ldb + k0 + lc]);
        }
    };

    const int S = K >> 5;
    if(NODEA){
        buildA(0); storeA(0);
        cpB(0,0); CP_COMMIT();
    } else {
        cpA(0,0);  cpB(0,0);  CP_COMMIT();
        cpA(32,1); cpB(32,1); CP_COMMIT();   // S >= 4 for all our shapes
    }

    for(int s=0; s<S; s++){
        bool more = (s+1 < S);
        int buf;
        if(NODEA){
            CP_WAIT0();
            __syncthreads();
            if(more){
                cpB((s+1)<<5, (s+1)&1);
                CP_COMMIT();
                buildA((s+1)<<5);            // LDGs drain under mma
            }
            buf = s & 1;
        } else {
            if(s < S-1) CP_WAIT1(); else CP_WAIT0();
            __syncthreads();
            if(s+2 < S){
                cpA((s+2)<<5, (s+2)%3);
                cpB((s+2)<<5, (s+2)%3);
                CP_COMMIT();
            }
            buf = s % 3;
        }

        uint32_t sAa = smbase + buf*16384;
        uint32_t sBa = sAa + 8192;
#pragma unroll
        for(int kh=0; kh<2; kh++){
            int ka = kh*2;
            uint32_t a[2][4];
#pragma unroll
            for(int mi=0; mi<2; mi++){
                uint32_t addr = sAa + abase[mi] + ((((amb[mi] + ka + aj) ^ asw[mi]))<<4);
                ldsm4(a[mi][0], a[mi][1], a[mi][2], a[mi][3], addr);
            }
#pragma unroll
            for(int p=0; p<4; p++){
                uint32_t b0,b1r,b2,b3;
                uint32_t addr = sBa + bbase[p] + ((((bmb[p] + ka + bj) ^ bsw[p]))<<4);
                ldsm4(b0, b1r, b2, b3, addr);
                mma16(acc[0][2*p  ], a[0], b0, b1r);
                mma16(acc[0][2*p+1], a[0], b2, b3);
                mma16(acc[1][2*p  ], a[1], b0, b1r);
                mma16(acc[1][2*p+1], a[1], b2, b3);
            }
        }
        if(NODEA && more) storeA((s+1)&1);   // after mma: hides LDG latency
    }

#pragma unroll
    for(int mi=0; mi<2; mi++){
#pragma unroll
        for(int rr=0; rr<2; rr++){
            int row = m0 + wm + mi*16 + qr + rr*8;
            size_t crow = (size_t)row*ldc;
#pragma unroll
            for(int ni=0; ni<8; ni++){
                int col = n0 + wn + ni*8 + qc*2;
                float v0 = (rr==0 ? acc[mi][ni].x : acc[mi][ni].z);
                float v1 = (rr==0 ? acc[mi][ni].y : acc[mi][ni].w);
                if(BIAS){ v0 += bias[col]; v1 += bias[col+1]; }
                if(ACT==1){ v0 = eluf(v0); v1 = eluf(v1); }
                if(OUTH){
                    *(__half2*)&(((__half*)Cp)[crow + col]) = __floats2half2_rn(v0, v1);
                } else {
                    *(float2*)&(((float*)Cp)[crow + col]) = make_float2(v0, v1);
                }
            }
        }
    }
}

// ================= fused edge GEMM + NW1 GEMM, 512 threads =================
__global__ void __launch_bounds__(512,1)
k_edge_fused(const __half* __restrict__ PQ,
             const int* __restrict__ srcp, const int* __restrict__ dstp,
             const float* __restrict__ b1,
             const __half* __restrict__ W2h, const float* __restrict__ b2,
             const __half* __restrict__ NW1h,
             float* __restrict__ agg2)
{
    extern __shared__ __align__(16) char esm[];
    const int m0 = blockIdx.x*128;
    const int tid  = threadIdx.x;
    const int warp = tid >> 5, lane = tid & 31;
    const int wm  = (warp >> 2)*32;
    const int wn  = (warp &  3)*64;
    const int wn2 = (warp &  3)*32;
    const int qr = lane >> 2, qc = lane & 3;
    const uint32_t smbase = (uint32_t)__cvta_generic_to_shared(esm);
    const uint32_t AOFF = 0, BOFF = 16384, MOFF = 0, NOFF = 65536;

    const int j  = lane >> 3, rl = lane & 7;
    const int aj = j >> 1;
    const int bj = j & 1;
    int abase[2], asw[2], amb[2];
#pragma unroll
    for(int mi=0; mi<2; mi++){
        int m = wm + mi*16 + (j&1)*8 + rl;
        abase[mi] = (m>>1)*128; asw[mi] = (m>>1)&7; amb[mi] = (m&1)*4;
    }
    int bbase[4], bsw[4], bmb[4];
#pragma unroll
    for(int p=0; p<4; p++){
        int n = wn + p*16 + (j>>1)*8 + rl;
        bbase[p] = (n>>1)*128; bsw[p] = (n>>1)&7; bmb[p] = (n&1)*4;
    }
    int cbase[2], csw[2], cmb[2];
#pragma unroll
    for(int p=0; p<2; p++){
        int n = wn2 + p*16 + (j>>1)*8 + rl;
        cbase[p] = (n>>1)*128; csw[p] = (n>>1)&7; cmb[p] = (n&1)*4;
    }

    const int ar = tid >> 2;
    const int ac = (tid & 3) * 8;
    const __half *ap, *aq;
    {
        int grow = m0 + ar;
        int e = grow >> 6, srow = grow & 63;
        ap = PQ + ((size_t)__ldg(&srcp[e])*64 + srow)*512;
        aq = PQ + ((size_t)__ldg(&dstp[e])*64 + srow)*512 + 256;
    }
    const uint32_t aslot = (uint32_t)(swatom(ar, (tid&3)));

    float4 acc[2][8];
#pragma unroll
    for(int mi=0;mi<2;mi++)
#pragma unroll
        for(int ni=0;ni<8;ni++) acc[mi][ni] = make_float4(0.f,0.f,0.f,0.f);

    uint4 ra;

    auto buildA = [&](int k0){
        int kc = k0 + ac;
        uint4 pv = *(const uint4*)(ap + kc);
        uint4 qv = *(const uint4*)(aq + kc);
        float4 bb0 = *(const float4*)&b1[kc];
        float4 bb1 = *(const float4*)&b1[kc+4];
        const __half2* phh = (const __half2*)&pv;
        const __half2* qhh = (const __half2*)&qv;
        float bl[8] = {bb0.x,bb0.y,bb0.z,bb0.w,bb1.x,bb1.y,bb1.z,bb1.w};
        uint32_t o[4];
#pragma unroll
        for(int w=0; w<4; w++){
            float2 pf = __half22float2(phh[w]);
            float2 qf = __half22float2(qhh[w]);
            o[w] = f2h2(eluf(pf.x+qf.x+bl[2*w]), eluf(pf.y+qf.y+bl[2*w+1]));
        }
        ra = make_uint4(o[0],o[1],o[2],o[3]);
    };
    auto storeA = [&](int st){
        *(uint4*)(esm + AOFF + st*8192 + aslot) = ra;
    };
    auto cpW2 = [&](int s, int st){
        int k0 = s << 5;
#pragma unroll
        for(int it=0; it<2; it++){
            int idx = tid + it*512;
            int r = idx >> 2, c = (idx & 3)*8;
            cpa16(smbase + BOFF + st*16384 + swatom(r, idx&3),
                  &W2h[(size_t)r*256 + k0 + c]);
        }
    };

    // ---- phase 1 mainloop: 1 barrier/stage, loads before mma, STS after ----
    buildA(0); storeA(0);
    cpW2(0, 0);
    CP_COMMIT();

    for(int s=0; s<8; s++){
        bool more = (s+1 < 8);
        CP_WAIT0();
        __syncthreads();
        if(more){
            cpW2(s+1, (s+1)&1);
            CP_COMMIT();
            buildA((s+1)<<5);
        }

        uint32_t sAa = smbase + AOFF + (s&1)*8192;
        uint32_t sBa = smbase + BOFF + (s&1)*16384;
#pragma unroll
        for(int kh=0; kh<2; kh++){
            int ka = kh*2;
            uint32_t a[2][4];
#pragma unroll
            for(int mi=0; mi<2; mi++){
                uint32_t addr = sAa + abase[mi] + ((((amb[mi] + ka + aj) ^ asw[mi]))<<4);
                ldsm4(a[mi][0], a[mi][1], a[mi][2], a[mi][3], addr);
            }
#pragma unroll
            for(int p=0; p<4; p++){
                uint32_t b0,b1r,b2r,b3;
                uint32_t addr = sBa + bbase[p] + ((((bmb[p] + ka + bj) ^ bsw[p]))<<4);
                ldsm4(b0, b1r, b2r, b3, addr);
                mma16(acc[0][2*p  ], a[0], b0, b1r);
                mma16(acc[0][2*p+1], a[0], b2r, b3);
                mma16(acc[1][2*p  ], a[1], b0, b1r);
                mma16(acc[1][2*p+1], a[1], b2r, b3);
            }
        }
        if(more) storeA((s+1)&1);
    }
    __syncthreads();   // all phase-1 smem reads done before overlay

    // ---- stream first NW1 tile while writing handoff ----
    {
        int idx = tid;
        int n = idx >> 2, kc = (idx & 3)*8;
        cpa16(smbase + NOFF + swatom(n, idx&3), &NW1h[(size_t)n*256 + kc]);
        CP_COMMIT();
    }

    // ---- handoff: m2 = elu(acc + b2) into smem slices (overlay) ----
#pragma unroll
    for(int mi=0; mi<2; mi++){
#pragma unroll
        for(int rr=0; rr<2; rr++){
            int row = wm + mi*16 + qr + rr*8;
#pragma unroll
            for(int ni=0; ni<8; ni++){
                int col = wn + ni*8 + qc*2;
                float v0 = (rr==0 ? acc[mi][ni].x : acc[mi][ni].z) + __ldg(&b2[col]);
                float v1 = (rr==0 ? acc[mi][ni].y : acc[mi][ni].w) + __ldg(&b2[col+1]);
                v0 = eluf(v0); v1 = eluf(v1);
                int ksl = col >> 5, c = col & 31;
                uint32_t off = MOFF + (uint32_t)ksl*8192 + swatom(row, c>>3) + (c&7)*2;
                *(__half2*)(esm + off) = __floats2half2_rn(v0, v1);
            }
        }
    }

    // ---- phase 2: z = m2 @ NW1^T (128x128x256), 1 barrier/stage ----
    float4 acc2[2][4];
#pragma unroll
    for(int mi=0;mi<2;mi++)
#pragma unroll
        for(int ni=0;ni<4;ni++) acc2[mi][ni] = make_float4(0.f,0.f,0.f,0.f);

    auto cpN = [&](int s, int st){
        int k0 = s << 5;
        int idx = tid;
        int n = idx >> 2, kc = (idx & 3)*8;
        cpa16(smbase + NOFF + st*8192 + swatom(n, idx&3),
              &NW1h[(size_t)n*256 + k0 + kc]);
    };

    for(int s2=0; s2<8; s2++){
        bool more = (s2+1 < 8);
        CP_WAIT0();
        __syncthreads();
        if(more){ cpN(s2+1, (s2+1)&1); CP_COMMIT(); }

        uint32_t sAa = smbase + MOFF + s2*8192;
        uint32_t sBa = smbase + NOFF + (s2&1)*8192;
#pragma unroll
        for(int kh=0; kh<2; kh++){
            int ka = kh*2;
            uint32_t a[2][4];
#pragma unroll
            for(int mi=0; mi<2; mi++){
                uint32_t addr = sAa + abase[mi] + ((((amb[mi] + ka + aj) ^ asw[mi]))<<4);
                ldsm4(a[mi][0], a[mi][1], a[mi][2], a[mi][3], addr);
            }
#pragma unroll
            for(int p=0; p<2; p++){
                uint32_t b0,b1r,b2r,b3;
                uint32_t addr = sBa + cbase[p] + ((((cmb[p] + ka + bj) ^ csw[p]))<<4);
                ldsm4(b0, b1r, b2r, b3, addr);
                mma16(acc2[0][2*p  ], a[0], b0, b1r);
                mma16(acc2[0][2*p+1], a[0], b2r, b3);
                mma16(acc2[1][2*p  ], a[1], b0, b1r);
                mma16(acc2[1][2*p+1], a[1], b2r, b3);
            }
        }
    }

    // ---- epilogue: scatter z (raw, pre-bias) into agg2 ----
#pragma unroll
    for(int mi=0; mi<2; mi++){
#pragma unroll
        for(int rr=0; rr<2; rr++){
            int row = m0 + wm + mi*16 + qr + rr*8;
            int e = row >> 6, s = row & 63;
            size_t crow = (size_t)(__ldg(&dstp[e])*64 + s)*128;
#pragma unroll
            for(int ni=0; ni<4; ni++){
                int col = wn2 + ni*8 + qc*2;
                float v0 = (rr==0 ? acc2[mi][ni].x : acc2[mi][ni].z);
                float v1 = (rr==0 ? acc2[mi][ni].y : acc2[mi][ni].w);
                redv2(&agg2[crow + col], v0, v1);
            }
        }
    }
}

// ================= tensor-core persistent LSTM =================
__global__ void __launch_bounds__(256,1)
k_lstm_mma(const __half* __restrict__ Whh, const __half* __restrict__ gates){
    __shared__ __align__(16) __half hA[16*136];
    __shared__ float G[8][512];
    const int tid = threadIdx.x, warp = tid>>5, lane = tid&31;
    const int nb = blockIdx.x*8;
    const int wn = warp*64;
    const uint32_t hAb = (uint32_t)__cvta_generic_to_shared(hA);

    float cst[4] = {0.f,0.f,0.f,0.f};
    for(int i=tid; i<16*136; i+=256) hA[i] = __float2half(0.f);

    uint32_t bf[8][8][2];
    {
        int bn = lane>>2, bk = (lane&3)*2;
#pragma unroll
        for(int nt=0; nt<8; nt++)
#pragma unroll
        for(int kt=0; kt<8; kt++){
            const __half* p = Whh + (size_t)(wn + nt*8 + bn)*128 + kt*16 + bk;
            bf[nt][kt][0] = *(const uint32_t*)p;
            bf[nt][kt][1] = *(const uint32_t*)(p + 8);
        }
    }
    __syncthreads();

    const int j = lane>>3, rl = lane&7;
    const int arow = (j&1)*8 + rl;
    const int cr = lane>>2, cc = (lane&3)*2;

    for(int t=0; t<64; t++){
        uint32_t gvr[8];
#pragma unroll
        for(int nt=0; nt<8; nt++)
            gvr[nt] = *(const uint32_t*)&gates[((size_t)(nb+cr)*64 + t)*512 + wn + nt*8 + cc];

        uint32_t a[8][4];
#pragma unroll
        for(int kt=0; kt<8; kt++){
            uint32_t addr = hAb + arow*272 + (uint32_t)((kt*2 + (j>>1))*16);
            ldsm4(a[kt][0], a[kt][1], a[kt][2], a[kt][3], addr);
        }
        float4 acc[8];
#pragma unroll
        for(int nt=0; nt<8; nt++) acc[nt] = make_float4(0.f,0.f,0.f,0.f);
#pragma unroll
        for(int kt=0; kt<8; kt++)
#pragma unroll
            for(int nt=0; nt<8; nt++)
                mma16(acc[nt], a[kt], bf[nt][kt][0], bf[nt][kt][1]);

#pragma unroll
        for(int nt=0; nt<8; nt++){
            int col = wn + nt*8 + cc;
            float2 gf = __half22float2(*(__half2*)&gvr[nt]);
            G[cr][col]   = acc[nt].x + gf.x;
            G[cr][col+1] = acc[nt].y + gf.y;
        }
        __syncthreads();

#pragma unroll
        for(int q=0; q<4; q++){
            int idx = q*256 + tid;
            int n = idx>>7, jj = idx&127;
            float ig=G[n][jj], fg=G[n][128+jj], gg=G[n][256+jj], og=G[n][384+jj];
            float cn = sigf(fg)*cst[q] + sigf(ig)*tanhfast(gg);
            cst[q] = cn;
            float h = sigf(og)*tanhfast(cn);
            hA[n*136 + jj] = __float2half(h);
            if(t==63) g_h[(size_t)(nb+n)*128 + jj] = h;
        }
        __syncthreads();
    }
}

// ---------------- output heads ----------------
__global__ void k_heads(const float* __restrict__ Wm, const float* __restrict__ bm,
                        const float* __restrict__ Wt, const float* __restrict__ bt,
                        const float* __restrict__ We, const float* __restrict__ be,
                        float* __restrict__ out){
    int n = blockIdx.x;
    int l = threadIdx.x;
    float sm=0.f, st=0.f, se=0.f;
    for(int jj=l;jj<128;jj+=32){
        float h = g_h[(size_t)n*128 + jj];
        sm += h*Wm[jj]; st += h*Wt[jj]; se += h*We[jj];
    }
#pragma unroll
    for(int o=16;o;o>>=1){
        sm += __shfl_down_sync(0xffffffffu, sm, o);
        st += __shfl_down_sync(0xffffffffu, st, o);
        se += __shfl_down_sync(0xffffffffu, se, o);
    }
    if(l==0){
        out[n]            = sm + bm[0];
        out[N_NODES + n]  = st + bt[0];
        out[2*N_NODES + n]= se + be[0];
    }
}

// ---------------- host launcher ----------------
extern "C" void kernel_launch(void* const* d_in, const int* in_sizes, int n_in,
                              void* d_out, int out_size)
{
    const int*   edge  = (const int*)  d_in[0];
    const float* itime = (const float*)d_in[1];
    const float* iev   = (const float*)d_in[2];
    const int*   ann   = (const int*)  d_in[3];
    const float* emb   = (const float*)d_in[4];
    const float* W_in  = (const float*)d_in[5];
    const float* b_in  = (const float*)d_in[6];
    const float* nW1   = (const float*)d_in[7];
    const float* nb1   = (const float*)d_in[8];
    const float* nW2   = (const float*)d_in[9];
    const float* nb2   = (const float*)d_in[10];
    const float* aW1   = (const float*)d_in[11];
    const float* ab1   = (const float*)d_in[12];
    const float* aW2   = (const float*)d_in[13];
    const float* ab2   = (const float*)d_in[14];
    const float* Wih   = (const float*)d_in[15];
    const float* Whh   = (const float*)d_in[16];
    const float* bih   = (const float*)d_in[17];
    const float* bhh   = (const float*)d_in[18];
    const float* Wm    = (const float*)d_in[19];
    const float* bm    = (const float*)d_in[20];
    const float* Wt    = (const float*)d_in[21];
    const float* bt    = (const float*)d_in[22];
    const float* We    = (const float*)d_in[23];
    const float* be    = (const float*)d_in[24];
    float* out = (float*)d_out;

    const int* src = edge;
    const int* dst = edge + NEDGE;

    __half *pxh, *pnfh, *pPQh, *pgatesh;
    __half *pWinh, *pW1ph, *pW2h, *pNW1h, *pNW2h, *pWihh, *pWhhh;
    float *pagg, *pinvdeg, *pbsum;
    cudaGetSymbolAddress((void**)&pxh,    g_xh);
    cudaGetSymbolAddress((void**)&pnfh,   g_nfh);
    cudaGetSymbolAddress((void**)&pPQh,   g_PQh);
    cudaGetSymbolAddress((void**)&pgatesh,g_gatesh);
    cudaGetSymbolAddress((void**)&pWinh,  g_Winh);
    cudaGetSymbolAddress((void**)&pW1ph,  g_W1ph);
    cudaGetSymbolAddress((void**)&pW2h,   g_W2h);
    cudaGetSymbolAddress((void**)&pNW1h,  g_NW1h);
    cudaGetSymbolAddress((void**)&pNW2h,  g_NW2h);
    cudaGetSymbolAddress((void**)&pWihh,  g_Wihh);
    cudaGetSymbolAddress((void**)&pWhhh,  g_Whhh);
    cudaGetSymbolAddress((void**)&pagg,   g_agg);
    cudaGetSymbolAddress((void**)&pinvdeg,g_invdeg);
    cudaGetSymbolAddress((void**)&pbsum,  g_bsum);

    cudaFuncSetAttribute(k_edge_fused, cudaFuncAttributeMaxDynamicSharedMemorySize, 81920);

    // #1 combo (prep+deg+build_x+zero agg), #2 Win GEMM, #3 PQ GEMM, #4 edge_fused (ncu slot)
    k_combo<<<COMBO_BLOCKS,256>>>(W_in, Wih, Whh, bih, bhh, aW1, aW2, nW1, nW2,
                                  itime, iev, ann, emb, dst);
    k_gemm<0,true,true,false><<<dim3(NS/128,1),256>>>(
        pxh,256, nullptr,nullptr,nullptr, pWinh,256, b_in, pnfh,128, 256);

    for(int l=0; l<2; l++){
        const float* B1 = ab1 + (size_t)l*256;
        const float* B2 = ab2 + (size_t)l*256;
        const float* NB1= nb1 + (size_t)l*128;
        const float* NB2= nb2 + (size_t)l*128;
        __half* W1p = pW1ph + (size_t)l*65536;
        __half* W2h = pW2h  + (size_t)l*65536;
        __half* NW1h= pNW1h + (size_t)l*32768;
        __half* NW2h= pNW2h + (size_t)l*16384;

        // [P|Q] = nf @ W1p^T -> fp16 [NS,512]
        k_gemm<0,false,true,false><<<dim3(NS/128,4),256>>>(
            pnfh,128, nullptr,nullptr,nullptr, W1p,128, nullptr, pPQh,512, 128);

        if(l == 1)   // layer-0 agg zeroed in combo
            cudaMemsetAsync(pagg, 0, (size_t)NS*128*sizeof(float));

        // fused edge+NW1 GEMM with red.v2 scatter
        k_edge_fused<<<ES/128,512,81920>>>(pPQh, src, dst, B1, W2h, B2, NW1h, pagg);

        // NW2 GEMM with fused node1 (A = elu(agg*invdeg + NB1) built on the fly)
        k_gemm<1,true,true,true><<<dim3(NS/128,1),256>>>(
            nullptr,128, pagg, pinvdeg, NB1, NW2h,128, NB2, pnfh,128, 128);
    }

    // LSTM: input gates for all timesteps, then tensor-core recurrence
    k_gemm<0,true,true,false><<<dim3(NS/128,4),256>>>(
        pnfh,128, nullptr,nullptr,nullptr, pWihh,128, pbsum, pgatesh,512, 128);
    k_lstm_mma<<<128,256>>>(pWhhh, pgatesh);

    k_heads<<<N_NODES,32>>>(Wm,bm,Wt,bt,We,be,out);
}

// round 14
// speedup vs baseline: 1.1507x; 1.1507x over previous
#include <cuda_runtime.h>
#include <cuda_fp16.h>
#include <math.h>
#include <stdint.h>

#define N_NODES 1024
#define SEQ     64
#define NEDGE   4096
#define NS      (N_NODES*SEQ)   /* 65536  */
#define ES      (NEDGE*SEQ)     /* 262144 */

// ---------------- scratch (device globals) ----------------
__device__ __half g_xh[NS*256];
__device__ __half g_nfh[NS*128];
__device__ __half g_PQh[NS*512];
__device__ float  g_agg[NS*128];
__device__ __half g_gatesh[NS*512];
__device__ __half g_Winh[128*256];
__device__ __half g_W1ph[2*512*128];
__device__ __half g_W2h[2*256*256];
__device__ __half g_NW1h[2*128*256];
__device__ __half g_NW2h[2*128*128];
__device__ __half g_Wihh[512*128];
__device__ __half g_Whhh[512*128];
__device__ float  g_invdeg[N_NODES];
__device__ float  g_h[N_NODES*128];
__device__ float  g_bsum[512];

// ---------------- helpers ----------------
__device__ __forceinline__ float eluf(float v){ return v > 0.f ? v : (__expf(v) - 1.f); }
__device__ __forceinline__ float sigf(float v){ return 1.f/(1.f+__expf(-v)); }
__device__ __forceinline__ float tanhfast(float v){ return 1.f - 2.f/(__expf(2.f*v)+1.f); }
__device__ __forceinline__ uint32_t f2h2(float lo, float hi){
    __half2 h = __floats2half2_rn(lo, hi);
    return *(uint32_t*)&h;
}
__device__ __forceinline__ void mma16(float4 &d, const uint32_t a[4], uint32_t b0, uint32_t b1){
    asm volatile("mma.sync.aligned.m16n8k16.row.col.f32.f16.f16.f32 "
        "{%0,%1,%2,%3}, {%4,%5,%6,%7}, {%8,%9}, {%0,%1,%2,%3};\n"
        : "+f"(d.x), "+f"(d.y), "+f"(d.z), "+f"(d.w)
        : "r"(a[0]), "r"(a[1]), "r"(a[2]), "r"(a[3]), "r"(b0), "r"(b1));
}
__device__ __forceinline__ void ldsm4(uint32_t &r0, uint32_t &r1, uint32_t &r2, uint32_t &r3, uint32_t addr){
    asm volatile("ldmatrix.sync.aligned.m8n8.x4.shared.b16 {%0,%1,%2,%3}, [%4];"
        : "=r"(r0), "=r"(r1), "=r"(r2), "=r"(r3) : "r"(addr));
}
__device__ __forceinline__ void redv2(float* p, float v0, float v1){
    asm volatile("red.global.add.v2.f32 [%0], {%1, %2};" :: "l"(p), "f"(v0), "f"(v1) : "memory");
}
__device__ __forceinline__ void cpa16(uint32_t dst, const void* src){
    asm volatile("cp.async.cg.shared.global [%0], [%1], 16;" :: "r"(dst), "l"(src));
}
#define CP_COMMIT() asm volatile("cp.async.commit_group;" ::: "memory")
#define CP_WAIT0()  asm volatile("cp.async.wait_group 0;" ::: "memory")
#define CP_WAIT1()  asm volatile("cp.async.wait_group 1;" ::: "memory")
// swizzled 16B-atom byte offset, 2 rows per 128B line, 4 k-atoms per row
__device__ __forceinline__ int swatom(int r, int katom){
    return (r>>1)*128 + ((((r&1)*4 + katom) ^ ((r>>1)&7))<<4);
}

// ---------------- degree ----------------
__global__ void k_zero_deg(){
    int i = blockIdx.x*blockDim.x + threadIdx.x;
    if(i < N_NODES) g_invdeg[i] = 0.f;
}
__global__ void k_deg(const int* __restrict__ dst){
    int e = blockIdx.x*blockDim.x + threadIdx.x;
    if(e < NEDGE) atomicAdd(&g_invdeg[dst[e]], 1.f);
}
__global__ void k_fin_deg(){
    int i = blockIdx.x*blockDim.x + threadIdx.x;
    if(i < N_NODES){ float d = g_invdeg[i]; g_invdeg[i] = 1.f/fmaxf(d,1.f); }
}

// ---------------- merged weight prep (both layers, once) ----------------
__global__ void k_prep_all(const float* __restrict__ W_in,
                           const float* __restrict__ Wih, const float* __restrict__ Whh,
                           const float* __restrict__ bih, const float* __restrict__ bhh,
                           const float* __restrict__ aW1, const float* __restrict__ aW2,
                           const float* __restrict__ nW1, const float* __restrict__ nW2){
    int i = blockIdx.x*256 + threadIdx.x;   // 0..65535
    if(i < 128*256) g_Winh[i] = __float2half(W_in[i]);
    g_Wihh[i] = __float2half(Wih[i]);
    g_Whhh[i] = __float2half(Whh[i]);
    if(i < 512) g_bsum[i] = bih[i] + bhh[i];
#pragma unroll
    for(int l=0; l<2; l++){
        const float* W1 = aW1 + (size_t)l*65536;
        int o = i >> 8, k = i & 255;
        __half v = __float2half(W1[i]);
        if(k < 128) g_W1ph[l*65536 + o*128 + k] = v;
        else        g_W1ph[l*65536 + (256+o)*128 + (k-128)] = v;
        g_W2h[l*65536 + i] = __float2half(aW2[(size_t)l*65536 + i]);
        if(i < 128*256) g_NW1h[l*32768 + i] = __float2half(nW1[(size_t)l*32768 + i]);
        if(i < 128*128) g_NW2h[l*16384 + i] = __float2half(nW2[(size_t)l*16384 + i]);
    }
}

// ---------------- build x, vectorized half2 ----------------
__global__ void k_build_x2(const float* __restrict__ itime, const float* __restrict__ iev,
                           const int* __restrict__ ann, const float* __restrict__ emb){
    int idx = blockIdx.x*blockDim.x + threadIdx.x;   // over NS*128 half2
    int row = idx >> 7, cp = idx & 127;
    float e = __ldg(&iev[row]);
    __half2 o;
    if(cp < 63){
        const float* ep = emb + (size_t)__ldg(&ann[row])*127 + cp*2;
        o = __floats2half2_rn(__ldg(ep), __ldg(ep+1));
    } else if(cp == 63){
        o = __floats2half2_rn(__ldg(&emb[(size_t)__ldg(&ann[row])*127 + 126]), e);
    } else {
        int j = cp - 64;
        float pos = exp2f(13.287712379549449f * (float)j * (1.0f/64.0f));
        float r = __ldg(&itime[row]) / pos;
        float sv = __sinf(r), cv = __cosf(r);
        if(e == 0.f){ sv = 0.f; cv = 0.f; }
        o = __floats2half2_rn(sv, cv);
    }
    *(__half2*)&g_xh[(size_t)idx*2] = o;
}

// ================= generic FP16 tensor-core GEMM (cp.async, 2-stage, 1 barrier/stage) =================
// NODEA: A built on the fly from fp32 agg: elu(agg*invdeg + nb1) -> fp16.
template<int ACT, bool BIAS, bool OUTH, bool NODEA>
__global__ void __launch_bounds__(256)
k_gemm(const __half* __restrict__ A, int lda,
       const float* __restrict__ aggf, const float* __restrict__ invdeg,
       const float* __restrict__ nb1,
       const __half* __restrict__ B, int ldb,
       const float* __restrict__ bias,
       void* __restrict__ Cp, int ldc, int K)
{
    __shared__ __align__(16) char sm[2*16384];
    const int m0 = blockIdx.x*128, n0 = blockIdx.y*128;
    const int tid  = threadIdx.x;
    const int warp = tid >> 5, lane = tid & 31;
    const int wm = (warp >> 1)*32;
    const int wn = (warp &  1)*64;
    const int qr = lane >> 2, qc = lane & 3;
    const uint32_t smbase = (uint32_t)__cvta_generic_to_shared(sm);

    const int j  = lane >> 3, rl = lane & 7;
    const int aj = j >> 1;
    const int bj = j & 1;
    int abase[2], asw[2], amb[2];
#pragma unroll
    for(int mi=0; mi<2; mi++){
        int m = wm + mi*16 + (j&1)*8 + rl;
        abase[mi] = (m>>1)*128; asw[mi] = (m>>1)&7; amb[mi] = (m&1)*4;
    }
    int bbase[4], bsw[4], bmb[4];
#pragma unroll
    for(int p=0; p<4; p++){
        int n = wn + p*16 + (j>>1)*8 + rl;
        bbase[p] = (n>>1)*128; bsw[p] = (n>>1)&7; bmb[p] = (n&1)*4;
    }

    float4 acc[2][8];
#pragma unroll
    for(int mi=0;mi<2;mi++)
#pragma unroll
        for(int ni=0;ni<8;ni++) acc[mi][ni] = make_float4(0.f,0.f,0.f,0.f);

    const int lr = tid >> 2;
    const int lc = (tid & 3) * 8;
    const int lk = tid & 3;

    uint4 raN[2];

    auto buildA = [&](int k0){
#pragma unroll
        for(int it=0; it<2; it++){
            int r = lr + it*64;
            const float* p = &aggf[(size_t)(m0+r)*128 + k0 + lc];
            float sc = __ldg(&invdeg[(m0+r) >> 6]);
            float4 v0 = *(const float4*)p;
            float4 v1 = *(const float4*)(p+4);
            float4 b0 = *(const float4*)&nb1[k0+lc];
            float4 b1v = *(const float4*)&nb1[k0+lc+4];
            raN[it] = make_uint4(
                f2h2(eluf(v0.x*sc+b0.x),  eluf(v0.y*sc+b0.y)),
                f2h2(eluf(v0.z*sc+b0.z),  eluf(v0.w*sc+b0.w)),
                f2h2(eluf(v1.x*sc+b1v.x), eluf(v1.y*sc+b1v.y)),
                f2h2(eluf(v1.z*sc+b1v.z), eluf(v1.w*sc+b1v.w)));
        }
    };
    auto storeA = [&](int st){
#pragma unroll
        for(int it=0; it<2; it++)
            *(uint4*)(sm + st*16384 + swatom(lr + it*64, lk)) = raN[it];
    };
    auto cpA = [&](int k0, int st){
#pragma unroll
        for(int it=0; it<2; it++){
            int r = lr + it*64;
            cpa16(smbase + st*16384 + swatom(r, lk), &A[(size_t)(m0+r)*lda + k0 + lc]);
        }
    };
    auto cpB = [&](int k0, int st){
#pragma unroll
        for(int it=0; it<2; it++){
            int r = lr + it*64;
            cpa16(smbase + st*16384 + 8192 + swatom(r, lk), &B[(size_t)(n0+r)*ldb + k0 + lc]);
        }
    };

    const int S = K >> 5;
    if(NODEA){ buildA(0); storeA(0); } else { cpA(0,0); }
    cpB(0,0);
    CP_COMMIT();

    for(int s=0; s<S; s++){
        bool more = (s+1 < S);
        CP_WAIT0();
        __syncthreads();
        if(more){
            if(!NODEA) cpA((s+1)<<5, (s+1)&1);
            cpB((s+1)<<5, (s+1)&1);
            CP_COMMIT();
            if(NODEA) buildA((s+1)<<5);   // LDGs drain under mma
        }

        uint32_t sAa = smbase + (s&1)*16384;
        uint32_t sBa = sAa + 8192;
#pragma unroll
        for(int kh=0; kh<2; kh++){
            int ka = kh*2;
            uint32_t a[2][4];
#pragma unroll
            for(int mi=0; mi<2; mi++){
                uint32_t addr = sAa + abase[mi] + ((((amb[mi] + ka + aj) ^ asw[mi]))<<4);
                ldsm4(a[mi][0], a[mi][1], a[mi][2], a[mi][3], addr);
            }
#pragma unroll
            for(int p=0; p<4; p++){
                uint32_t b0,b1r,b2,b3;
                uint32_t addr = sBa + bbase[p] + ((((bmb[p] + ka + bj) ^ bsw[p]))<<4);
                ldsm4(b0, b1r, b2, b3, addr);
                mma16(acc[0][2*p  ], a[0], b0, b1r);
                mma16(acc[0][2*p+1], a[0], b2, b3);
                mma16(acc[1][2*p  ], a[1], b0, b1r);
                mma16(acc[1][2*p+1], a[1], b2, b3);
            }
        }
        if(NODEA && more) storeA((s+1)&1);   // after mma: hides LDG latency
    }

#pragma unroll
    for(int mi=0; mi<2; mi++){
#pragma unroll
        for(int rr=0; rr<2; rr++){
            int row = m0 + wm + mi*16 + qr + rr*8;
            size_t crow = (size_t)row*ldc;
#pragma unroll
            for(int ni=0; ni<8; ni++){
                int col = n0 + wn + ni*8 + qc*2;
                float v0 = (rr==0 ? acc[mi][ni].x : acc[mi][ni].z);
                float v1 = (rr==0 ? acc[mi][ni].y : acc[mi][ni].w);
                if(BIAS){ v0 += bias[col]; v1 += bias[col+1]; }
                if(ACT==1){ v0 = eluf(v0); v1 = eluf(v1); }
                if(OUTH){
                    *(__half2*)&(((__half*)Cp)[crow + col]) = __floats2half2_rn(v0, v1);
                } else {
                    *(float2*)&(((float*)Cp)[crow + col]) = make_float2(v0, v1);
                }
            }
        }
    }
}

// ================= fused edge GEMM + NW1 GEMM, barrier-minimal =================
// smem 192KB: A full 64KB @0 (8 slices; overlaid by m2 after phase 1),
//             W2 full 128KB @65536 (8 slices; overlaid by NW1 full 64KB in phase 2).
// Phase 1: build all A + cp.async all W2 (2 groups) -> 8 stages with 2 barriers.
// Phase 2: NW1 full load + m2 handoff -> 8 stages with 0 barriers.
__global__ void __launch_bounds__(512,1)
k_edge_fused(const __half* __restrict__ PQ,
             const int* __restrict__ srcp, const int* __restrict__ dstp,
             const float* __restrict__ b1,
             const __half* __restrict__ W2h, const float* __restrict__ b2,
             const __half* __restrict__ NW1h,
             float* __restrict__ agg2)
{
    extern __shared__ __align__(16) char esm[];
    const int m0 = blockIdx.x*128;
    const int tid  = threadIdx.x;
    const int warp = tid >> 5, lane = tid & 31;
    const int wm  = (warp >> 2)*32;
    const int wn  = (warp &  3)*64;
    const int wn2 = (warp &  3)*32;
    const int qr = lane >> 2, qc = lane & 3;
    const uint32_t smbase = (uint32_t)__cvta_generic_to_shared(esm);
    const uint32_t AOFF = 0, BOFF = 65536, NOFF = 65536;

    const int j  = lane >> 3, rl = lane & 7;
    const int aj = j >> 1;
    const int bj = j & 1;
    int abase[2], asw[2], amb[2];
#pragma unroll
    for(int mi=0; mi<2; mi++){
        int m = wm + mi*16 + (j&1)*8 + rl;
        abase[mi] = (m>>1)*128; asw[mi] = (m>>1)&7; amb[mi] = (m&1)*4;
    }
    int bbase[4], bsw[4], bmb[4];
#pragma unroll
    for(int p=0; p<4; p++){
        int n = wn + p*16 + (j>>1)*8 + rl;
        bbase[p] = (n>>1)*128; bsw[p] = (n>>1)&7; bmb[p] = (n&1)*4;
    }
    int cbase[2], csw[2], cmb[2];
#pragma unroll
    for(int p=0; p<2; p++){
        int n = wn2 + p*16 + (j>>1)*8 + rl;
        cbase[p] = (n>>1)*128; csw[p] = (n>>1)&7; cmb[p] = (n&1)*4;
    }

    // ---- cp.async full W2 (8 slices; 2 commit groups of 4 slices) ----
#pragma unroll
    for(int it=0; it<16; it++){
        int idx = tid + it*512;           // 0..8191
        int sl = idx >> 10, idx2 = idx & 1023;
        int r = idx2 >> 2, cch = (idx2 & 3)*8;
        cpa16(smbase + BOFF + sl*16384 + swatom(r, idx2&3),
              &W2h[(size_t)r*256 + sl*32 + cch]);
        if(it == 7) CP_COMMIT();
    }
    CP_COMMIT();

    // ---- build ALL of A (8 uint4 per thread, fixed row) ----
    const int ar = tid >> 2, a4 = tid & 3;
    const __half *ap, *aq;
    {
        int grow = m0 + ar;
        int e = grow >> 6, srow = grow & 63;
        ap = PQ + ((size_t)__ldg(&srcp[e])*64 + srow)*512;
        aq = PQ + ((size_t)__ldg(&dstp[e])*64 + srow)*512 + 256;
    }
#pragma unroll
    for(int it=0; it<8; it++){
        int kc = a4*8 + it*32;
        uint4 pv = *(const uint4*)(ap + kc);
        uint4 qv = *(const uint4*)(aq + kc);
        float4 bb0 = *(const float4*)&b1[kc];
        float4 bb1 = *(const float4*)&b1[kc+4];
        const __half2* phh = (const __half2*)&pv;
        const __half2* qhh = (const __half2*)&qv;
        float bl[8] = {bb0.x,bb0.y,bb0.z,bb0.w,bb1.x,bb1.y,bb1.z,bb1.w};
        uint32_t o[4];
#pragma unroll
        for(int w=0; w<4; w++){
            float2 pf = __half22float2(phh[w]);
            float2 qf = __half22float2(qhh[w]);
            o[w] = f2h2(eluf(pf.x+qf.x+bl[2*w]), eluf(pf.y+qf.y+bl[2*w+1]));
        }
        *(uint4*)(esm + AOFF + it*8192 + swatom(ar, a4)) = make_uint4(o[0],o[1],o[2],o[3]);
    }

    float4 acc[2][8];
#pragma unroll
    for(int mi=0;mi<2;mi++)
#pragma unroll
        for(int ni=0;ni<8;ni++) acc[mi][ni] = make_float4(0.f,0.f,0.f,0.f);

    // ---- phase 1: 8 stages, 2 barriers ----
    CP_WAIT1();
    __syncthreads();
#pragma unroll
    for(int s=0; s<8; s++){
        if(s == 4){ CP_WAIT0(); __syncthreads(); }
        uint32_t sAa = smbase + AOFF + s*8192;
        uint32_t sBa = smbase + BOFF + s*16384;
#pragma unroll
        for(int kh=0; kh<2; kh++){
            int ka = kh*2;
            uint32_t a[2][4];
#pragma unroll
            for(int mi=0; mi<2; mi++){
                uint32_t addr = sAa + abase[mi] + ((((amb[mi] + ka + aj) ^ asw[mi]))<<4);
                ldsm4(a[mi][0], a[mi][1], a[mi][2], a[mi][3], addr);
            }
#pragma unroll
            for(int p=0; p<4; p++){
                uint32_t b0,b1r,b2r,b3;
                uint32_t addr = sBa + bbase[p] + ((((bmb[p] + ka + bj) ^ bsw[p]))<<4);
                ldsm4(b0, b1r, b2r, b3, addr);
                mma16(acc[0][2*p  ], a[0], b0, b1r);
                mma16(acc[0][2*p+1], a[0], b2r, b3);
                mma16(acc[1][2*p  ], a[1], b0, b1r);
                mma16(acc[1][2*p+1], a[1], b2r, b3);
            }
        }
    }
    __syncthreads();   // all A / W2 reads done before overlays

    // ---- NW1 full load into dead W2 region ----
#pragma unroll
    for(int it=0; it<8; it++){
        int idx = tid + it*512;           // 0..4095
        int n = idx >> 5, cch = (idx & 31)*8;
        cpa16(smbase + NOFF + (cch>>5)*8192 + swatom(n, (cch&31)>>3),
              &NW1h[(size_t)n*256 + cch]);
    }
    CP_COMMIT();

    // ---- handoff: m2 = elu(acc + b2) over dead A region ----
#pragma unroll
    for(int mi=0; mi<2; mi++){
#pragma unroll
        for(int rr=0; rr<2; rr++){
            int row = wm + mi*16 + qr + rr*8;
#pragma unroll
            for(int ni=0; ni<8; ni++){
                int col = wn + ni*8 + qc*2;
                float v0 = (rr==0 ? acc[mi][ni].x : acc[mi][ni].z) + __ldg(&b2[col]);
                float v1 = (rr==0 ? acc[mi][ni].y : acc[mi][ni].w) + __ldg(&b2[col+1]);
                v0 = eluf(v0); v1 = eluf(v1);
                int ksl = col >> 5, c = col & 31;
                uint32_t off = AOFF + (uint32_t)ksl*8192 + swatom(row, c>>3) + (c&7)*2;
                *(__half2*)(esm + off) = __floats2half2_rn(v0, v1);
            }
        }
    }
    CP_WAIT0();
    __syncthreads();

    // ---- phase 2: z = m2 @ NW1^T, 8 stages, 0 barriers ----
    float4 acc2[2][4];
#pragma unroll
    for(int mi=0;mi<2;mi++)
#pragma unroll
        for(int ni=0;ni<4;ni++) acc2[mi][ni] = make_float4(0.f,0.f,0.f,0.f);

#pragma unroll
    for(int s2=0; s2<8; s2++){
        uint32_t sAa = smbase + AOFF + s2*8192;
        uint32_t sBa = smbase + NOFF + s2*8192;
#pragma unroll
        for(int kh=0; kh<2; kh++){
            int ka = kh*2;
            uint32_t a[2][4];
#pragma unroll
            for(int mi=0; mi<2; mi++){
                uint32_t addr = sAa + abase[mi] + ((((amb[mi] + ka + aj) ^ asw[mi]))<<4);
                ldsm4(a[mi][0], a[mi][1], a[mi][2], a[mi][3], addr);
            }
#pragma unroll
            for(int p=0; p<2; p++){
                uint32_t b0,b1r,b2r,b3;
                uint32_t addr = sBa + cbase[p] + ((((cmb[p] + ka + bj) ^ csw[p]))<<4);
                ldsm4(b0, b1r, b2r, b3, addr);
                mma16(acc2[0][2*p  ], a[0], b0, b1r);
                mma16(acc2[0][2*p+1], a[0], b2r, b3);
                mma16(acc2[1][2*p  ], a[1], b0, b1r);
                mma16(acc2[1][2*p+1], a[1], b2r, b3);
            }
        }
    }

    // ---- epilogue: scatter z (raw, pre-bias) into agg2 ----
#pragma unroll
    for(int mi=0; mi<2; mi++){
#pragma unroll
        for(int rr=0; rr<2; rr++){
            int row = m0 + wm + mi*16 + qr + rr*8;
            int e = row >> 6, s = row & 63;
            size_t crow = (size_t)(__ldg(&dstp[e])*64 + s)*128;
#pragma unroll
            for(int ni=0; ni<4; ni++){
                int col = wn2 + ni*8 + qc*2;
                float v0 = (rr==0 ? acc2[mi][ni].x : acc2[mi][ni].z);
                float v1 = (rr==0 ? acc2[mi][ni].y : acc2[mi][ni].w);
                redv2(&agg2[crow + col], v0, v1);
            }
        }
    }
}

// ================= tensor-core persistent LSTM =================
__global__ void __launch_bounds__(256,1)
k_lstm_mma(const __half* __restrict__ Whh, const __half* __restrict__ gates){
    __shared__ __align__(16) __half hA[16*136];
    __shared__ float G[8][512];
    const int tid = threadIdx.x, warp = tid>>5, lane = tid&31;
    const int nb = blockIdx.x*8;
    const int wn = warp*64;
    const uint32_t hAb = (uint32_t)__cvta_generic_to_shared(hA);

    float cst[4] = {0.f,0.f,0.f,0.f};
    for(int i=tid; i<16*136; i+=256) hA[i] = __float2half(0.f);

    uint32_t bf[8][8][2];
    {
        int bn = lane>>2, bk = (lane&3)*2;
#pragma unroll
        for(int nt=0; nt<8; nt++)
#pragma unroll
        for(int kt=0; kt<8; kt++){
            const __half* p = Whh + (size_t)(wn + nt*8 + bn)*128 + kt*16 + bk;
            bf[nt][kt][0] = *(const uint32_t*)p;
            bf[nt][kt][1] = *(const uint32_t*)(p + 8);
        }
    }
    __syncthreads();

    const int j = lane>>3, rl = lane&7;
    const int arow = (j&1)*8 + rl;
    const int cr = lane>>2, cc = (lane&3)*2;

    for(int t=0; t<64; t++){
        uint32_t gvr[8];
#pragma unroll
        for(int nt=0; nt<8; nt++)
            gvr[nt] = *(const uint32_t*)&gates[((size_t)(nb+cr)*64 + t)*512 + wn + nt*8 + cc];

        uint32_t a[8][4];
#pragma unroll
        for(int kt=0; kt<8; kt++){
            uint32_t addr = hAb + arow*272 + (uint32_t)((kt*2 + (j>>1))*16);
            ldsm4(a[kt][0], a[kt][1], a[kt][2], a[kt][3], addr);
        }
        float4 acc[8];
#pragma unroll
        for(int nt=0; nt<8; nt++) acc[nt] = make_float4(0.f,0.f,0.f,0.f);
#pragma unroll
        for(int kt=0; kt<8; kt++)
#pragma unroll
            for(int nt=0; nt<8; nt++)
                mma16(acc[nt], a[kt], bf[nt][kt][0], bf[nt][kt][1]);

#pragma unroll
        for(int nt=0; nt<8; nt++){
            int col = wn + nt*8 + cc;
            float2 gf = __half22float2(*(__half2*)&gvr[nt]);
            G[cr][col]   = acc[nt].x + gf.x;
            G[cr][col+1] = acc[nt].y + gf.y;
        }
        __syncthreads();

#pragma unroll
        for(int q=0; q<4; q++){
            int idx = q*256 + tid;
            int n = idx>>7, jj = idx&127;
            float ig=G[n][jj], fg=G[n][128+jj], gg=G[n][256+jj], og=G[n][384+jj];
            float cn = sigf(fg)*cst[q] + sigf(ig)*tanhfast(gg);
            cst[q] = cn;
            float h = sigf(og)*tanhfast(cn);
            hA[n*136 + jj] = __float2half(h);
            if(t==63) g_h[(size_t)(nb+n)*128 + jj] = h;
        }
        __syncthreads();
    }
}

// ---------------- output heads ----------------
__global__ void k_heads(const float* __restrict__ Wm, const float* __restrict__ bm,
                        const float* __restrict__ Wt, const float* __restrict__ bt,
                        const float* __restrict__ We, const float* __restrict__ be,
                        float* __restrict__ out){
    int n = blockIdx.x;
    int l = threadIdx.x;
    float sm=0.f, st=0.f, se=0.f;
    for(int jj=l;jj<128;jj+=32){
        float h = g_h[(size_t)n*128 + jj];
        sm += h*Wm[jj]; st += h*Wt[jj]; se += h*We[jj];
    }
#pragma unroll
    for(int o=16;o;o>>=1){
        sm += __shfl_down_sync(0xffffffffu, sm, o);
        st += __shfl_down_sync(0xffffffffu, st, o);
        se += __shfl_down_sync(0xffffffffu, se, o);
    }
    if(l==0){
        out[n]            = sm + bm[0];
        out[N_NODES + n]  = st + bt[0];
        out[2*N_NODES + n]= se + be[0];
    }
}

// ---------------- host launcher ----------------
extern "C" void kernel_launch(void* const* d_in, const int* in_sizes, int n_in,
                              void* d_out, int out_size)
{
    const int*   edge  = (const int*)  d_in[0];
    const float* itime = (const float*)d_in[1];
    const float* iev   = (const float*)d_in[2];
    const int*   ann   = (const int*)  d_in[3];
    const float* emb   = (const float*)d_in[4];
    const float* W_in  = (const float*)d_in[5];
    const float* b_in  = (const float*)d_in[6];
    const float* nW1   = (const float*)d_in[7];
    const float* nb1   = (const float*)d_in[8];
    const float* nW2   = (const float*)d_in[9];
    const float* nb2   = (const float*)d_in[10];
    const float* aW1   = (const float*)d_in[11];
    const float* ab1   = (const float*)d_in[12];
    const float* aW2   = (const float*)d_in[13];
    const float* ab2   = (const float*)d_in[14];
    const float* Wih   = (const float*)d_in[15];
    const float* Whh   = (const float*)d_in[16];
    const float* bih   = (const float*)d_in[17];
    const float* bhh   = (const float*)d_in[18];
    const float* Wm    = (const float*)d_in[19];
    const float* bm    = (const float*)d_in[20];
    const float* Wt    = (const float*)d_in[21];
    const float* bt    = (const float*)d_in[22];
    const float* We    = (const float*)d_in[23];
    const float* be    = (const float*)d_in[24];
    float* out = (float*)d_out;

    const int* src = edge;
    const int* dst = edge + NEDGE;

    __half *pxh, *pnfh, *pPQh, *pgatesh;
    __half *pWinh, *pW1ph, *pW2h, *pNW1h, *pNW2h, *pWihh, *pWhhh;
    float *pagg, *pinvdeg, *pbsum;
    cudaGetSymbolAddress((void**)&pxh,    g_xh);
    cudaGetSymbolAddress((void**)&pnfh,   g_nfh);
    cudaGetSymbolAddress((void**)&pPQh,   g_PQh);
    cudaGetSymbolAddress((void**)&pgatesh,g_gatesh);
    cudaGetSymbolAddress((void**)&pWinh,  g_Winh);
    cudaGetSymbolAddress((void**)&pW1ph,  g_W1ph);
    cudaGetSymbolAddress((void**)&pW2h,   g_W2h);
    cudaGetSymbolAddress((void**)&pNW1h,  g_NW1h);
    cudaGetSymbolAddress((void**)&pNW2h,  g_NW2h);
    cudaGetSymbolAddress((void**)&pWihh,  g_Wihh);
    cudaGetSymbolAddress((void**)&pWhhh,  g_Whhh);
    cudaGetSymbolAddress((void**)&pagg,   g_agg);
    cudaGetSymbolAddress((void**)&pinvdeg,g_invdeg);
    cudaGetSymbolAddress((void**)&pbsum,  g_bsum);

    cudaFuncSetAttribute(k_edge_fused, cudaFuncAttributeMaxDynamicSharedMemorySize, 196608);

    // prep + build_x + Win GEMM, then per-layer pipeline
    k_prep_all<<<256,256>>>(W_in, Wih, Whh, bih, bhh, aW1, aW2, nW1, nW2);
    k_build_x2<<<NS*128/256,256>>>(itime, iev, ann, emb);
    k_gemm<0,true,true,false><<<dim3(NS/128,1),256>>>(
        pxh,256, nullptr,nullptr,nullptr, pWinh,256, b_in, pnfh,128, 256);

    for(int l=0; l<2; l++){
        const float* B1 = ab1 + (size_t)l*256;
        const float* B2 = ab2 + (size_t)l*256;
        const float* NB1= nb1 + (size_t)l*128;
        const float* NB2= nb2 + (size_t)l*128;
        __half* W1p = pW1ph + (size_t)l*65536;
        __half* W2h = pW2h  + (size_t)l*65536;
        __half* NW1h= pNW1h + (size_t)l*32768;
        __half* NW2h= pNW2h + (size_t)l*16384;

        // [P|Q] = nf @ W1p^T -> fp16 [NS,512]
        k_gemm<0,false,true,false><<<dim3(NS/128,4),256>>>(
            pnfh,128, nullptr,nullptr,nullptr, W1p,128, nullptr, pPQh,512, 128);

        if(l == 0){  // degrees (only needed from the NW2 GEMM onward)
            k_zero_deg<<<4,256>>>();
            k_deg<<<(NEDGE+255)/256,256>>>(dst);
            k_fin_deg<<<4,256>>>();
        }

        // zero agg2 (128-wide), fused edge+NW1 GEMM with red.v2 scatter
        cudaMemsetAsync(pagg, 0, (size_t)NS*128*sizeof(float));
        k_edge_fused<<<ES/128,512,196608>>>(pPQh, src, dst, B1, W2h, B2, NW1h, pagg);

        // NW2 GEMM with fused node1 (A = elu(agg*invdeg + NB1) built on the fly)
        k_gemm<1,true,true,true><<<dim3(NS/128,1),256>>>(
            nullptr,128, pagg, pinvdeg, NB1, NW2h,128, NB2, pnfh,128, 128);
    }

    // LSTM: input gates for all timesteps, then tensor-core recurrence
    k_gemm<0,true,true,false><<<dim3(NS/128,4),256>>>(
        pnfh,128, nullptr,nullptr,nullptr, pWihh,128, pbsum, pgatesh,512, 128);
    k_lstm_mma<<<128,256>>>(pWhhh, pgatesh);

    k_heads<<<N_NODES,32>>>(Wm,bm,Wt,bt,We,be,out);
}

// round 15
// speedup vs baseline: 1.1717x; 1.0183x over previous
#include <cuda_runtime.h>
#include <cuda_fp16.h>
#include <math.h>
#include <stdint.h>

#define N_NODES 1024
#define SEQ     64
#define NEDGE   4096
#define NS      (N_NODES*SEQ)   /* 65536  */
#define ES      (NEDGE*SEQ)     /* 262144 */

// ---------------- scratch (device globals) ----------------
__device__ __half g_nfh[NS*128];
__device__ __half g_PQh[NS*512];
__device__ float  g_agg[NS*128];
__device__ __half g_gatesh[NS*512];
__device__ __half g_Winh[128*256];
__device__ __half g_W1ph[2*512*128];
__device__ __half g_W2h[2*256*256];
__device__ __half g_NW1h[2*128*256];
__device__ __half g_NW2h[2*128*128];
__device__ __half g_Wihh[512*128];
__device__ __half g_Whhh[512*128];
__device__ float  g_invdeg[N_NODES];
__device__ float  g_h[N_NODES*128];
__device__ float  g_bsum[512];

// ---------------- helpers ----------------
__device__ __forceinline__ float eluf(float v){ return v > 0.f ? v : (__expf(v) - 1.f); }
__device__ __forceinline__ float sigf(float v){ return 1.f/(1.f+__expf(-v)); }
__device__ __forceinline__ float tanhfast(float v){ return 1.f - 2.f/(__expf(2.f*v)+1.f); }
__device__ __forceinline__ uint32_t f2h2(float lo, float hi){
    __half2 h = __floats2half2_rn(lo, hi);
    return *(uint32_t*)&h;
}
__device__ __forceinline__ void mma16(float4 &d, const uint32_t a[4], uint32_t b0, uint32_t b1){
    asm volatile("mma.sync.aligned.m16n8k16.row.col.f32.f16.f16.f32 "
        "{%0,%1,%2,%3}, {%4,%5,%6,%7}, {%8,%9}, {%0,%1,%2,%3};\n"
        : "+f"(d.x), "+f"(d.y), "+f"(d.z), "+f"(d.w)
        : "r"(a[0]), "r"(a[1]), "r"(a[2]), "r"(a[3]), "r"(b0), "r"(b1));
}
__device__ __forceinline__ void ldsm4(uint32_t &r0, uint32_t &r1, uint32_t &r2, uint32_t &r3, uint32_t addr){
    asm volatile("ldmatrix.sync.aligned.m8n8.x4.shared.b16 {%0,%1,%2,%3}, [%4];"
        : "=r"(r0), "=r"(r1), "=r"(r2), "=r"(r3) : "r"(addr));
}
__device__ __forceinline__ void redv2(float* p, float v0, float v1){
    asm volatile("red.global.add.v2.f32 [%0], {%1, %2};" :: "l"(p), "f"(v0), "f"(v1) : "memory");
}
__device__ __forceinline__ void cpa16(uint32_t dst, const void* src){
    asm volatile("cp.async.cg.shared.global [%0], [%1], 16;" :: "r"(dst), "l"(src));
}
#define CP_COMMIT() asm volatile("cp.async.commit_group;" ::: "memory")
#define CP_WAIT0()  asm volatile("cp.async.wait_group 0;" ::: "memory")
#define CP_WAIT1()  asm volatile("cp.async.wait_group 1;" ::: "memory")
// swizzled 16B-atom byte offset, 2 rows per 128B line, 4 k-atoms per row
__device__ __forceinline__ int swatom(int r, int katom){
    return (r>>1)*128 + ((((r&1)*4 + katom) ^ ((r>>1)&7))<<4);
}

// ---------------- degree ----------------
__global__ void k_zero_deg(){
    int i = blockIdx.x*blockDim.x + threadIdx.x;
    if(i < N_NODES) g_invdeg[i] = 0.f;
}
__global__ void k_deg(const int* __restrict__ dst){
    int e = blockIdx.x*blockDim.x + threadIdx.x;
    if(e < NEDGE) atomicAdd(&g_invdeg[dst[e]], 1.f);
}
__global__ void k_fin_deg(){
    int i = blockIdx.x*blockDim.x + threadIdx.x;
    if(i < N_NODES){ float d = g_invdeg[i]; g_invdeg[i] = 1.f/fmaxf(d,1.f); }
}

// ---------------- merged weight prep (both layers, once) ----------------
__global__ void k_prep_all(const float* __restrict__ W_in,
                           const float* __restrict__ Wih, const float* __restrict__ Whh,
                           const float* __restrict__ bih, const float* __restrict__ bhh,
                           const float* __restrict__ aW1, const float* __restrict__ aW2,
                           const float* __restrict__ nW1, const float* __restrict__ nW2){
    int i = blockIdx.x*256 + threadIdx.x;   // 0..65535
    if(i < 128*256) g_Winh[i] = __float2half(W_in[i]);
    g_Wihh[i] = __float2half(Wih[i]);
    g_Whhh[i] = __float2half(Whh[i]);
    if(i < 512) g_bsum[i] = bih[i] + bhh[i];
#pragma unroll
    for(int l=0; l<2; l++){
        const float* W1 = aW1 + (size_t)l*65536;
        int o = i >> 8, k = i & 255;
        __half v = __float2half(W1[i]);
        if(k < 128) g_W1ph[l*65536 + o*128 + k] = v;
        else        g_W1ph[l*65536 + (256+o)*128 + (k-128)] = v;
        g_W2h[l*65536 + i] = __float2half(aW2[(size_t)l*65536 + i]);
        if(i < 128*256) g_NW1h[l*32768 + i] = __float2half(nW1[(size_t)l*32768 + i]);
        if(i < 128*128) g_NW2h[l*16384 + i] = __float2half(nW2[(size_t)l*16384 + i]);
    }
}

// ================= generic FP16 tensor-core GEMM (cp.async, 2-stage, 1 barrier/stage) =================
// AMODE: 0 = A from fp16 global (cp.async); 1 = A built from fp32 agg (elu(agg*invdeg+nb1));
//        2 = A built from input-embedding math (emb | events | temporal encoding).
// AGGZ: blocks with blockIdx.y==0 zero aggz rows [m0,m0+128) after the epilogue.
template<int ACT, bool BIAS, bool OUTH, int AMODE, bool AGGZ>
__global__ void __launch_bounds__(256)
k_gemm(const __half* __restrict__ A, int lda,
       const float* __restrict__ aggf, const float* __restrict__ invdeg,
       const float* __restrict__ nb1,
       const int* __restrict__ ann, const float* __restrict__ itime,
       const float* __restrict__ iev, const float* __restrict__ emb,
       const __half* __restrict__ B, int ldb,
       const float* __restrict__ bias,
       float* __restrict__ aggz,
       void* __restrict__ Cp, int ldc, int K)
{
    __shared__ __align__(16) char sm[2*16384];
    const int m0 = blockIdx.x*128, n0 = blockIdx.y*128;
    const int tid  = threadIdx.x;
    const int warp = tid >> 5, lane = tid & 31;
    const int wm = (warp >> 1)*32;
    const int wn = (warp &  1)*64;
    const int qr = lane >> 2, qc = lane & 3;
    const uint32_t smbase = (uint32_t)__cvta_generic_to_shared(sm);

    const int j  = lane >> 3, rl = lane & 7;
    const int aj = j >> 1;
    const int bj = j & 1;
    int abase[2], asw[2], amb[2];
#pragma unroll
    for(int mi=0; mi<2; mi++){
        int m = wm + mi*16 + (j&1)*8 + rl;
        abase[mi] = (m>>1)*128; asw[mi] = (m>>1)&7; amb[mi] = (m&1)*4;
    }
    int bbase[4], bsw[4], bmb[4];
#pragma unroll
    for(int p=0; p<4; p++){
        int n = wn + p*16 + (j>>1)*8 + rl;
        bbase[p] = (n>>1)*128; bsw[p] = (n>>1)&7; bmb[p] = (n&1)*4;
    }

    float4 acc[2][8];
#pragma unroll
    for(int mi=0;mi<2;mi++)
#pragma unroll
        for(int ni=0;ni<8;ni++) acc[mi][ni] = make_float4(0.f,0.f,0.f,0.f);

    const int lr = tid >> 2;
    const int lc = (tid & 3) * 8;
    const int lk = tid & 3;

    uint4 raN[2];

    auto buildA = [&](int k0){
#pragma unroll
        for(int it=0; it<2; it++){
            int r = lr + it*64;
            const float* p = &aggf[(size_t)(m0+r)*128 + k0 + lc];
            float sc = __ldg(&invdeg[(m0+r) >> 6]);
            float4 v0 = *(const float4*)p;
            float4 v1 = *(const float4*)(p+4);
            float4 b0 = *(const float4*)&nb1[k0+lc];
            float4 b1v = *(const float4*)&nb1[k0+lc+4];
            raN[it] = make_uint4(
                f2h2(eluf(v0.x*sc+b0.x),  eluf(v0.y*sc+b0.y)),
                f2h2(eluf(v0.z*sc+b0.z),  eluf(v0.w*sc+b0.w)),
                f2h2(eluf(v1.x*sc+b1v.x), eluf(v1.y*sc+b1v.y)),
                f2h2(eluf(v1.z*sc+b1v.z), eluf(v1.w*sc+b1v.w)));
        }
    };
    auto buildX = [&](int k0){
#pragma unroll
        for(int it=0; it<2; it++){
            int r = m0 + lr + it*64;
            float tt = __ldg(&itime[r]);
            float ev = __ldg(&iev[r]);
            const float* ep = emb + (size_t)__ldg(&ann[r])*127;
            int c0 = k0 + lc;
            uint32_t o[4];
#pragma unroll
            for(int w=0; w<4; w++){
                int c = c0 + w*2;    // even
                float v0, v1;
                if(c+1 < 127){
                    v0 = __ldg(ep+c); v1 = __ldg(ep+c+1);
                } else if(c == 126){
                    v0 = __ldg(ep+126); v1 = ev;
                } else {
                    int jj = (c-128) >> 1;
                    float pos = exp2f(13.287712379549449f * (float)jj * (1.0f/64.0f));
                    float rr = tt / pos;
                    v0 = __sinf(rr); v1 = __cosf(rr);
                    if(ev == 0.f){ v0 = 0.f; v1 = 0.f; }
                }
                o[w] = f2h2(v0, v1);
            }
            raN[it] = make_uint4(o[0],o[1],o[2],o[3]);
        }
    };
    auto storeA = [&](int st){
#pragma unroll
        for(int it=0; it<2; it++)
            *(uint4*)(sm + st*16384 + swatom(lr + it*64, lk)) = raN[it];
    };
    auto cpA = [&](int k0, int st){
#pragma unroll
        for(int it=0; it<2; it++){
            int r = lr + it*64;
            cpa16(smbase + st*16384 + swatom(r, lk), &A[(size_t)(m0+r)*lda + k0 + lc]);
        }
    };
    auto cpB = [&](int k0, int st){
#pragma unroll
        for(int it=0; it<2; it++){
            int r = lr + it*64;
            cpa16(smbase + st*16384 + 8192 + swatom(r, lk), &B[(size_t)(n0+r)*ldb + k0 + lc]);
        }
    };

    const int S = K >> 5;
    if(AMODE==1){ buildA(0); storeA(0); }
    else if(AMODE==2){ buildX(0); storeA(0); }
    else { cpA(0,0); }
    cpB(0,0);
    CP_COMMIT();

    for(int s=0; s<S; s++){
        bool more = (s+1 < S);
        CP_WAIT0();
        __syncthreads();
        if(more){
            if(AMODE==0) cpA((s+1)<<5, (s+1)&1);
            cpB((s+1)<<5, (s+1)&1);
            CP_COMMIT();
            if(AMODE==1) buildA((s+1)<<5);   // LDGs drain under mma
            if(AMODE==2) buildX((s+1)<<5);
        }

        uint32_t sAa = smbase + (s&1)*16384;
        uint32_t sBa = sAa + 8192;
#pragma unroll
        for(int kh=0; kh<2; kh++){
            int ka = kh*2;
            uint32_t a[2][4];
#pragma unroll
            for(int mi=0; mi<2; mi++){
                uint32_t addr = sAa + abase[mi] + ((((amb[mi] + ka + aj) ^ asw[mi]))<<4);
                ldsm4(a[mi][0], a[mi][1], a[mi][2], a[mi][3], addr);
            }
#pragma unroll
            for(int p=0; p<4; p++){
                uint32_t b0,b1r,b2,b3;
                uint32_t addr = sBa + bbase[p] + ((((bmb[p] + ka + bj) ^ bsw[p]))<<4);
                ldsm4(b0, b1r, b2, b3, addr);
                mma16(acc[0][2*p  ], a[0], b0, b1r);
                mma16(acc[0][2*p+1], a[0], b2, b3);
                mma16(acc[1][2*p  ], a[1], b0, b1r);
                mma16(acc[1][2*p+1], a[1], b2, b3);
            }
        }
        if(AMODE!=0 && more) storeA((s+1)&1);   // after mma: hides LDG latency
    }

#pragma unroll
    for(int mi=0; mi<2; mi++){
#pragma unroll
        for(int rr=0; rr<2; rr++){
            int row = m0 + wm + mi*16 + qr + rr*8;
            size_t crow = (size_t)row*ldc;
#pragma unroll
            for(int ni=0; ni<8; ni++){
                int col = n0 + wn + ni*8 + qc*2;
                float v0 = (rr==0 ? acc[mi][ni].x : acc[mi][ni].z);
                float v1 = (rr==0 ? acc[mi][ni].y : acc[mi][ni].w);
                if(BIAS){ v0 += bias[col]; v1 += bias[col+1]; }
                if(ACT==1){ v0 = eluf(v0); v1 = eluf(v1); }
                if(OUTH){
                    *(__half2*)&(((__half*)Cp)[crow + col]) = __floats2half2_rn(v0, v1);
                } else {
                    *(float2*)&(((float*)Cp)[crow + col]) = make_float2(v0, v1);
                }
            }
        }
    }

    if(AGGZ && blockIdx.y == 0){
        float4 z = make_float4(0.f,0.f,0.f,0.f);
        for(int i=tid; i<128*32; i+=256)
            ((float4*)&aggz[(size_t)(m0 + (i>>5))*128])[i & 31] = z;
    }
}

// ================= fused edge GEMM + NW1 GEMM, barrier-minimal =================
// smem 192KB: A full 64KB @0 (8 slices; overlaid by m2 after phase 1),
//             W2 full 128KB @65536 (8 slices; overlaid by NW1 full 64KB in phase 2).
__global__ void __launch_bounds__(512,1)
k_edge_fused(const __half* __restrict__ PQ,
             const int* __restrict__ srcp, const int* __restrict__ dstp,
             const float* __restrict__ b1,
             const __half* __restrict__ W2h, const float* __restrict__ b2,
             const __half* __restrict__ NW1h,
             float* __restrict__ agg2)
{
    extern __shared__ __align__(16) char esm[];
    const int m0 = blockIdx.x*128;
    const int tid  = threadIdx.x;
    const int warp = tid >> 5, lane = tid & 31;
    const int wm  = (warp >> 2)*32;
    const int wn  = (warp &  3)*64;
    const int wn2 = (warp &  3)*32;
    const int qr = lane >> 2, qc = lane & 3;
    const uint32_t smbase = (uint32_t)__cvta_generic_to_shared(esm);
    const uint32_t AOFF = 0, BOFF = 65536, NOFF = 65536;

    const int j  = lane >> 3, rl = lane & 7;
    const int aj = j >> 1;
    const int bj = j & 1;
    int abase[2], asw[2], amb[2];
#pragma unroll
    for(int mi=0; mi<2; mi++){
        int m = wm + mi*16 + (j&1)*8 + rl;
        abase[mi] = (m>>1)*128; asw[mi] = (m>>1)&7; amb[mi] = (m&1)*4;
    }
    int bbase[4], bsw[4], bmb[4];
#pragma unroll
    for(int p=0; p<4; p++){
        int n = wn + p*16 + (j>>1)*8 + rl;
        bbase[p] = (n>>1)*128; bsw[p] = (n>>1)&7; bmb[p] = (n&1)*4;
    }
    int cbase[2], csw[2], cmb[2];
#pragma unroll
    for(int p=0; p<2; p++){
        int n = wn2 + p*16 + (j>>1)*8 + rl;
        cbase[p] = (n>>1)*128; csw[p] = (n>>1)&7; cmb[p] = (n&1)*4;
    }

    // ---- cp.async full W2 (8 slices; 2 commit groups of 4 slices) ----
#pragma unroll
    for(int it=0; it<16; it++){
        int idx = tid + it*512;           // 0..8191
        int sl = idx >> 10, idx2 = idx & 1023;
        int r = idx2 >> 2, cch = (idx2 & 3)*8;
        cpa16(smbase + BOFF + sl*16384 + swatom(r, idx2&3),
              &W2h[(size_t)r*256 + sl*32 + cch]);
        if(it == 7) CP_COMMIT();
    }
    CP_COMMIT();

    // ---- build ALL of A (8 uint4 per thread, fixed row) ----
    const int ar = tid >> 2, a4 = tid & 3;
    const __half *ap, *aq;
    {
        int grow = m0 + ar;
        int e = grow >> 6, srow = grow & 63;
        ap = PQ + ((size_t)__ldg(&srcp[e])*64 + srow)*512;
        aq = PQ + ((size_t)__ldg(&dstp[e])*64 + srow)*512 + 256;
    }
#pragma unroll
    for(int it=0; it<8; it++){
        int kc = a4*8 + it*32;
        uint4 pv = *(const uint4*)(ap + kc);
        uint4 qv = *(const uint4*)(aq + kc);
        float4 bb0 = *(const float4*)&b1[kc];
        float4 bb1 = *(const float4*)&b1[kc+4];
        const __half2* phh = (const __half2*)&pv;
        const __half2* qhh = (const __half2*)&qv;
        float bl[8] = {bb0.x,bb0.y,bb0.z,bb0.w,bb1.x,bb1.y,bb1.z,bb1.w};
        uint32_t o[4];
#pragma unroll
        for(int w=0; w<4; w++){
            float2 pf = __half22float2(phh[w]);
            float2 qf = __half22float2(qhh[w]);
            o[w] = f2h2(eluf(pf.x+qf.x+bl[2*w]), eluf(pf.y+qf.y+bl[2*w+1]));
        }
        *(uint4*)(esm + AOFF + it*8192 + swatom(ar, a4)) = make_uint4(o[0],o[1],o[2],o[3]);
    }

    float4 acc[2][8];
#pragma unroll
    for(int mi=0;mi<2;mi++)
#pragma unroll
        for(int ni=0;ni<8;ni++) acc[mi][ni] = make_float4(0.f,0.f,0.f,0.f);

    // ---- phase 1: 8 stages, 2 barriers ----
    CP_WAIT1();
    __syncthreads();
#pragma unroll
    for(int s=0; s<8; s++){
        if(s == 4){ CP_WAIT0(); __syncthreads(); }
        uint32_t sAa = smbase + AOFF + s*8192;
        uint32_t sBa = smbase + BOFF + s*16384;
#pragma unroll
        for(int kh=0; kh<2; kh++){
            int ka = kh*2;
            uint32_t a[2][4];
#pragma unroll
            for(int mi=0; mi<2; mi++){
                uint32_t addr = sAa + abase[mi] + ((((amb[mi] + ka + aj) ^ asw[mi]))<<4);
                ldsm4(a[mi][0], a[mi][1], a[mi][2], a[mi][3], addr);
            }
#pragma unroll
            for(int p=0; p<4; p++){
                uint32_t b0,b1r,b2r,b3;
                uint32_t addr = sBa + bbase[p] + ((((bmb[p] + ka + bj) ^ bsw[p]))<<4);
                ldsm4(b0, b1r, b2r, b3, addr);
                mma16(acc[0][2*p  ], a[0], b0, b1r);
                mma16(acc[0][2*p+1], a[0], b2r, b3);
                mma16(acc[1][2*p  ], a[1], b0, b1r);
                mma16(acc[1][2*p+1], a[1], b2r, b3);
            }
        }
    }
    __syncthreads();   // all A / W2 reads done before overlays

    // ---- NW1 full load into dead W2 region ----
#pragma unroll
    for(int it=0; it<8; it++){
        int idx = tid + it*512;           // 0..4095
        int n = idx >> 5, cch = (idx & 31)*8;
        cpa16(smbase + NOFF + (cch>>5)*8192 + swatom(n, (cch&31)>>3),
              &NW1h[(size_t)n*256 + cch]);
    }
    CP_COMMIT();

    // ---- handoff: m2 = elu(acc + b2) over dead A region ----
#pragma unroll
    for(int mi=0; mi<2; mi++){
#pragma unroll
        for(int rr=0; rr<2; rr++){
            int row = wm + mi*16 + qr + rr*8;
#pragma unroll
            for(int ni=0; ni<8; ni++){
                int col = wn + ni*8 + qc*2;
                float v0 = (rr==0 ? acc[mi][ni].x : acc[mi][ni].z) + __ldg(&b2[col]);
                float v1 = (rr==0 ? acc[mi][ni].y : acc[mi][ni].w) + __ldg(&b2[col+1]);
                v0 = eluf(v0); v1 = eluf(v1);
                int ksl = col >> 5, c = col & 31;
                uint32_t off = AOFF + (uint32_t)ksl*8192 + swatom(row, c>>3) + (c&7)*2;
                *(__half2*)(esm + off) = __floats2half2_rn(v0, v1);
            }
        }
    }
    CP_WAIT0();
    __syncthreads();

    // ---- phase 2: z = m2 @ NW1^T, 8 stages, 0 barriers ----
    float4 acc2[2][4];
#pragma unroll
    for(int mi=0;mi<2;mi++)
#pragma unroll
        for(int ni=0;ni<4;ni++) acc2[mi][ni] = make_float4(0.f,0.f,0.f,0.f);

#pragma unroll
    for(int s2=0; s2<8; s2++){
        uint32_t sAa = smbase + AOFF + s2*8192;
        uint32_t sBa = smbase + NOFF + s2*8192;
#pragma unroll
        for(int kh=0; kh<2; kh++){
            int ka = kh*2;
            uint32_t a[2][4];
#pragma unroll
            for(int mi=0; mi<2; mi++){
                uint32_t addr = sAa + abase[mi] + ((((amb[mi] + ka + aj) ^ asw[mi]))<<4);
                ldsm4(a[mi][0], a[mi][1], a[mi][2], a[mi][3], addr);
            }
#pragma unroll
            for(int p=0; p<2; p++){
                uint32_t b0,b1r,b2r,b3;
                uint32_t addr = sBa + cbase[p] + ((((cmb[p] + ka + bj) ^ csw[p]))<<4);
                ldsm4(b0, b1r, b2r, b3, addr);
                mma16(acc2[0][2*p  ], a[0], b0, b1r);
                mma16(acc2[0][2*p+1], a[0], b2r, b3);
                mma16(acc2[1][2*p  ], a[1], b0, b1r);
                mma16(acc2[1][2*p+1], a[1], b2r, b3);
            }
        }
    }

    // ---- epilogue: scatter z (raw, pre-bias) into agg2 ----
#pragma unroll
    for(int mi=0; mi<2; mi++){
#pragma unroll
        for(int rr=0; rr<2; rr++){
            int row = m0 + wm + mi*16 + qr + rr*8;
            int e = row >> 6, s = row & 63;
            size_t crow = (size_t)(__ldg(&dstp[e])*64 + s)*128;
#pragma unroll
            for(int ni=0; ni<4; ni++){
                int col = wn2 + ni*8 + qc*2;
                float v0 = (rr==0 ? acc2[mi][ni].x : acc2[mi][ni].z);
                float v1 = (rr==0 ? acc2[mi][ni].y : acc2[mi][ni].w);
                redv2(&agg2[crow + col], v0, v1);
            }
        }
    }
}

// ================= tensor-core persistent LSTM =================
__global__ void __launch_bounds__(256,1)
k_lstm_mma(const __half* __restrict__ Whh, const __half* __restrict__ gates){
    __shared__ __align__(16) __half hA[16*136];
    __shared__ float G[8][512];
    const int tid = threadIdx.x, warp = tid>>5, lane = tid&31;
    const int nb = blockIdx.x*8;
    const int wn = warp*64;
    const uint32_t hAb = (uint32_t)__cvta_generic_to_shared(hA);

    float cst[4] = {0.f,0.f,0.f,0.f};
    for(int i=tid; i<16*136; i+=256) hA[i] = __float2half(0.f);

    uint32_t bf[8][8][2];
    {
        int bn = lane>>2, bk = (lane&3)*2;
#pragma unroll
        for(int nt=0; nt<8; nt++)
#pragma unroll
        for(int kt=0; kt<8; kt++){
            const __half* p = Whh + (size_t)(wn + nt*8 + bn)*128 + kt*16 + bk;
            bf[nt][kt][0] = *(const uint32_t*)p;
            bf[nt][kt][1] = *(const uint32_t*)(p + 8);
        }
    }
    __syncthreads();

    const int j = lane>>3, rl = lane&7;
    const int arow = (j&1)*8 + rl;
    const int cr = lane>>2, cc = (lane&3)*2;

    for(int t=0; t<64; t++){
        uint32_t gvr[8];
#pragma unroll
        for(int nt=0; nt<8; nt++)
            gvr[nt] = *(const uint32_t*)&gates[((size_t)(nb+cr)*64 + t)*512 + wn + nt*8 + cc];

        uint32_t a[8][4];
#pragma unroll
        for(int kt=0; kt<8; kt++){
            uint32_t addr = hAb + arow*272 + (uint32_t)((kt*2 + (j>>1))*16);
            ldsm4(a[kt][0], a[kt][1], a[kt][2], a[kt][3], addr);
        }
        float4 acc[8];
#pragma unroll
        for(int nt=0; nt<8; nt++) acc[nt] = make_float4(0.f,0.f,0.f,0.f);
#pragma unroll
        for(int kt=0; kt<8; kt++)
#pragma unroll
            for(int nt=0; nt<8; nt++)
                mma16(acc[nt], a[kt], bf[nt][kt][0], bf[nt][kt][1]);

#pragma unroll
        for(int nt=0; nt<8; nt++){
            int col = wn + nt*8 + cc;
            float2 gf = __half22float2(*(__half2*)&gvr[nt]);
            G[cr][col]   = acc[nt].x + gf.x;
            G[cr][col+1] = acc[nt].y + gf.y;
        }
        __syncthreads();

#pragma unroll
        for(int q=0; q<4; q++){
            int idx = q*256 + tid;
            int n = idx>>7, jj = idx&127;
            float ig=G[n][jj], fg=G[n][128+jj], gg=G[n][256+jj], og=G[n][384+jj];
            float cn = sigf(fg)*cst[q] + sigf(ig)*tanhfast(gg);
            cst[q] = cn;
            float h = sigf(og)*tanhfast(cn);
            hA[n*136 + jj] = __float2half(h);
            if(t==63) g_h[(size_t)(nb+n)*128 + jj] = h;
        }
        __syncthreads();
    }
}

// ---------------- output heads ----------------
__global__ void k_heads(const float* __restrict__ Wm, const float* __restrict__ bm,
                        const float* __restrict__ Wt, const float* __restrict__ bt,
                        const float* __restrict__ We, const float* __restrict__ be,
                        float* __restrict__ out){
    int n = blockIdx.x;
    int l = threadIdx.x;
    float sm=0.f, st=0.f, se=0.f;
    for(int jj=l;jj<128;jj+=32){
        float h = g_h[(size_t)n*128 + jj];
        sm += h*Wm[jj]; st += h*Wt[jj]; se += h*We[jj];
    }
#pragma unroll
    for(int o=16;o;o>>=1){
        sm += __shfl_down_sync(0xffffffffu, sm, o);
        st += __shfl_down_sync(0xffffffffu, st, o);
        se += __shfl_down_sync(0xffffffffu, se, o);
    }
    if(l==0){
        out[n]            = sm + bm[0];
        out[N_NODES + n]  = st + bt[0];
        out[2*N_NODES + n]= se + be[0];
    }
}

// ---------------- host launcher ----------------
extern "C" void kernel_launch(void* const* d_in, const int* in_sizes, int n_in,
                              void* d_out, int out_size)
{
    const int*   edge  = (const int*)  d_in[0];
    const float* itime = (const float*)d_in[1];
    const float* iev   = (const float*)d_in[2];
    const int*   ann   = (const int*)  d_in[3];
    const float* emb   = (const float*)d_in[4];
    const float* W_in  = (const float*)d_in[5];
    const float* b_in  = (const float*)d_in[6];
    const float* nW1   = (const float*)d_in[7];
    const float* nb1   = (const float*)d_in[8];
    const float* nW2   = (const float*)d_in[9];
    const float* nb2   = (const float*)d_in[10];
    const float* aW1   = (const float*)d_in[11];
    const float* ab1   = (const float*)d_in[12];
    const float* aW2   = (const float*)d_in[13];
    const float* ab2   = (const float*)d_in[14];
    const float* Wih   = (const float*)d_in[15];
    const float* Whh   = (const float*)d_in[16];
    const float* bih   = (const float*)d_in[17];
    const float* bhh   = (const float*)d_in[18];
    const float* Wm    = (const float*)d_in[19];
    const float* bm    = (const float*)d_in[20];
    const float* Wt    = (const float*)d_in[21];
    const float* bt    = (const float*)d_in[22];
    const float* We    = (const float*)d_in[23];
    const float* be    = (const float*)d_in[24];
    float* out = (float*)d_out;

    const int* src = edge;
    const int* dst = edge + NEDGE;

    __half *pnfh, *pPQh, *pgatesh;
    __half *pWinh, *pW1ph, *pW2h, *pNW1h, *pNW2h, *pWihh, *pWhhh;
    float *pagg, *pinvdeg, *pbsum;
    cudaGetSymbolAddress((void**)&pnfh,   g_nfh);
    cudaGetSymbolAddress((void**)&pPQh,   g_PQh);
    cudaGetSymbolAddress((void**)&pgatesh,g_gatesh);
    cudaGetSymbolAddress((void**)&pWinh,  g_Winh);
    cudaGetSymbolAddress((void**)&pW1ph,  g_W1ph);
    cudaGetSymbolAddress((void**)&pW2h,   g_W2h);
    cudaGetSymbolAddress((void**)&pNW1h,  g_NW1h);
    cudaGetSymbolAddress((void**)&pNW2h,  g_NW2h);
    cudaGetSymbolAddress((void**)&pWihh,  g_Wihh);
    cudaGetSymbolAddress((void**)&pWhhh,  g_Whhh);
    cudaGetSymbolAddress((void**)&pagg,   g_agg);
    cudaGetSymbolAddress((void**)&pinvdeg,g_invdeg);
    cudaGetSymbolAddress((void**)&pbsum,  g_bsum);

    cudaFuncSetAttribute(k_edge_fused, cudaFuncAttributeMaxDynamicSharedMemorySize, 196608);

    // prep, then Win GEMM with fused input-embedding build (AMODE=2)
    k_prep_all<<<256,256>>>(W_in, Wih, Whh, bih, bhh, aW1, aW2, nW1, nW2);
    k_gemm<0,true,true,2,false><<<dim3(NS/128,1),256>>>(
        nullptr,0, nullptr,nullptr,nullptr, ann,itime,iev,emb,
        pWinh,256, b_in, nullptr, pnfh,128, 256);

    for(int l=0; l<2; l++){
        const float* B1 = ab1 + (size_t)l*256;
        const float* B2 = ab2 + (size_t)l*256;
        const float* NB1= nb1 + (size_t)l*128;
        const float* NB2= nb2 + (size_t)l*128;
        __half* W1p = pW1ph + (size_t)l*65536;
        __half* W2h = pW2h  + (size_t)l*65536;
        __half* NW1h= pNW1h + (size_t)l*32768;
        __half* NW2h= pNW2h + (size_t)l*16384;

        // [P|Q] = nf @ W1p^T -> fp16 [NS,512]; AGGZ zeroes agg rows for this layer
        k_gemm<0,false,true,0,true><<<dim3(NS/128,4),256>>>(
            pnfh,128, nullptr,nullptr,nullptr, nullptr,nullptr,nullptr,nullptr,
            W1p,128, nullptr, pagg, pPQh,512, 128);

        if(l == 0){  // degrees (only needed from the NW2 GEMM onward)
            k_zero_deg<<<4,256>>>();
            k_deg<<<(NEDGE+255)/256,256>>>(dst);
            k_fin_deg<<<4,256>>>();
        }

        // fused edge+NW1 GEMM with red.v2 scatter
        k_edge_fused<<<ES/128,512,196608>>>(pPQh, src, dst, B1, W2h, B2, NW1h, pagg);

        // NW2 GEMM with fused node1 (A = elu(agg*invdeg + NB1) built on the fly)
        k_gemm<1,true,true,1,false><<<dim3(NS/128,1),256>>>(
            nullptr,128, pagg, pinvdeg, NB1, nullptr,nullptr,nullptr,nullptr,
            NW2h,128, NB2, nullptr, pnfh,128, 128);
    }

    // LSTM: input gates for all timesteps, then tensor-core recurrence
    k_gemm<0,true,true,0,false><<<dim3(NS/128,4),256>>>(
        pnfh,128, nullptr,nullptr,nullptr, nullptr,nullptr,nullptr,nullptr,
        pWihh,128, pbsum, nullptr, pgatesh,512, 128);
    k_lstm_mma<<<128,256>>>(pWhhh, pgatesh);

    k_heads<<<N_NODES,32>>>(Wm,bm,Wt,bt,We,be,out);
}